// round 13
// baseline (speedup 1.0000x reference)
#include <cuda_runtime.h>
#include <cuda_fp16.h>
#include <cuda_bf16.h>

// RoadGNN: GCN(2->32) -> ReLU -> GAT(32->2x32, mean heads) -> ReLU -> GCN(32->1)
// Counting-sort CSR: cursor array pre-initialized to offsets (single atomic in fill,
// no off-gather, no rank array). GCN1 in input space. GAT weights via factored
// exponentials (zero MUFU in edge loops), fp16 feature gathers.

#define MAXN 100000
#define MAXE 1600000
#define MAXEP (MAXE + 3 * MAXN + 32)

// ---------------- scratch ----------------
__device__ int      g_deg[MAXN];        // zeroed by k_gcn2 tail each call
__device__ int      g_off[MAXN];
__device__ int      g_cur[MAXN];        // re-initialized to off by k_scan23 each call
__device__ __align__(16) int g_csr[MAXEP];
__device__ int      g_bsum[128];
__device__ float    g_dinv[MAXN];
__device__ __align__(8) float2 g_xt[MAXN];   // dinv[n] * x[n]
__device__ __half   g_hgh[MAXN * 64];        // GAT linear out fp16 (h0|h1)
__device__ __align__(8) float2 g_ps[MAXN];   // exp(0.2*a_src) per head
__device__ __align__(8) float2 g_qs[MAXN];   // exp(0.2*a_dst) per head
__device__ float    g_z[MAXN];

// ---------------- helpers ----------------
__device__ __forceinline__ float pow5(float t) { float t2 = t * t; return t2 * t2 * t; }
__device__ __forceinline__ int block_is64(const int* ei32, int* sh) {
    if (threadIdx.x < 32) {
        int bad = (ei32[2 * threadIdx.x + 1] != 0);
        unsigned b = __ballot_sync(0xffffffffu, bad);
        if (threadIdx.x == 0) *sh = (b == 0u);
    }
    __syncthreads();
    return *sh;
}

// ---------------- kernels ----------------

// launch 1: in-degree count only
__global__ void k_degcount(const void* __restrict__ ei, int E) {
    __shared__ int sh;
    int is64 = block_is64((const int*)ei, &sh);
    int e = blockIdx.x * blockDim.x + threadIdx.x;
    if (e >= E) return;
    int c;
    if (is64) c = (int)((const long long*)ei)[E + e];
    else      c = ((const int*)ei)[E + e];
    atomicAdd(&g_deg[c], 1);
}

// launch 2: block-local scan of 4-padded degrees
__global__ void k_scan1(int n) {
    __shared__ int sh[1024];
    int tid = threadIdx.x;
    int i = blockIdx.x * 1024 + tid;
    int v = (i < n) ? ((g_deg[i] + 3) & ~3) : 0;
    sh[tid] = v;
    __syncthreads();
#pragma unroll
    for (int d = 1; d < 1024; d <<= 1) {
        int t = (tid >= d) ? sh[tid - d] : 0;
        __syncthreads();
        sh[tid] += t;
        __syncthreads();
    }
    if (i < n) g_off[i] = sh[tid] - v;
    if (tid == 1023) g_bsum[blockIdx.x] = sh[1023];
}

// launch 3: finish scan; init cursor=off; compute dinv + xt
__global__ void k_scan23(const float* __restrict__ x, int n, int nb) {
    __shared__ int spre;
    int tid = threadIdx.x;
    if (tid < 32) {
        int p = 0;
        for (int k = tid; k < blockIdx.x; k += 32) p += g_bsum[k];
#pragma unroll
        for (int o = 16; o; o >>= 1) p += __shfl_down_sync(0xffffffffu, p, o);
        if (tid == 0) spre = p;
    }
    __syncthreads();
    int i = blockIdx.x * 1024 + tid;
    if (i < n) {
        int o = g_off[i] + spre;
        g_off[i] = o;
        g_cur[i] = o;                      // cursor starts at bucket base
        float d = rsqrtf((float)(g_deg[i] + 1));
        g_dinv[i] = d;
        float2 xv = *(const float2*)&x[2 * i];
        g_xt[i] = make_float2(d * xv.x, d * xv.y);
    }
}

// launch 4 (ncu slot): CSR fill — single spread atomic, no off gather
__global__ void k_fill(const void* __restrict__ ei, int E) {
    __shared__ int sh;
    int is64 = block_is64((const int*)ei, &sh);
    int e = blockIdx.x * blockDim.x + threadIdx.x;
    if (e >= E) return;
    int r, c;
    if (is64) {
        const long long* p = (const long long*)ei;
        r = (int)p[e]; c = (int)p[E + e];
    } else {
        const int* p = (const int*)ei;
        r = p[e]; c = p[E + e];
    }
    g_csr[atomicAdd(&g_cur[c], 1)] = r;
}

// launch 5: warp/node. Lane-parallel xt gather (GCN1 in input space),
// h1 = relu(dinv*(agg@W1)+b1), GAT linear, p/q exp factors.
__global__ void k_layer1(const float* __restrict__ W1, const float* __restrict__ b1,
                         const float* __restrict__ Wg,
                         const float* __restrict__ attS, const float* __restrict__ attD, int n) {
    __shared__ float sWg[32 * 64];
    int tid = threadIdx.x;
    for (int i = tid; i < 2048; i += blockDim.x) sWg[i] = Wg[i];
    __syncthreads();

    int node = (blockIdx.x * blockDim.x + tid) >> 5;
    int lane = tid & 31;
    if (node >= n) return;

    int off = g_off[node], deg = g_deg[node];
    float ax = 0.f, ay = 0.f;
    for (int base = 0; base < deg; base += 32) {
        if (base + lane < deg) {
            int r = g_csr[off + base + lane];
            float2 v = g_xt[r];
            ax += v.x; ay += v.y;
        }
    }
#pragma unroll
    for (int o = 16; o; o >>= 1) {
        ax += __shfl_xor_sync(0xffffffffu, ax, o);
        ay += __shfl_xor_sync(0xffffffffu, ay, o);
    }
    float2 self = g_xt[node];
    float d = g_dinv[node];
    ax = d * (ax + self.x);
    ay = d * (ay + self.y);

    float h1 = fmaxf(fmaf(ax, W1[lane], fmaf(ay, W1[32 + lane], b1[lane])), 0.f);

    float o0 = 0.f, o1 = 0.f;
#pragma unroll
    for (int i = 0; i < 32; i++) {
        float hv = __shfl_sync(0xffffffffu, h1, i);
        o0 = fmaf(hv, sWg[i * 64 + lane], o0);
        o1 = fmaf(hv, sWg[i * 64 + 32 + lane], o1);
    }
    g_hgh[node * 64 + lane]      = __float2half(o0);
    g_hgh[node * 64 + 32 + lane] = __float2half(o1);

    float as0 = o0 * attS[lane];
    float as1 = o1 * attS[32 + lane];
    float ad0 = o0 * attD[lane];
    float ad1 = o1 * attD[32 + lane];
#pragma unroll
    for (int o = 16; o; o >>= 1) {
        as0 += __shfl_down_sync(0xffffffffu, as0, o);
        as1 += __shfl_down_sync(0xffffffffu, as1, o);
        ad0 += __shfl_down_sync(0xffffffffu, ad0, o);
        ad1 += __shfl_down_sync(0xffffffffu, ad1, o);
    }
    if (lane == 0) {
        g_ps[node] = make_float2(__expf(0.2f * as0), __expf(0.2f * as1));
        g_qs[node] = make_float2(__expf(0.2f * ad0), __expf(0.2f * ad1));
    }
}

// launch 6: warp/node GAT. Phase A: lane-parallel multiplicative weights
// (t = p[r]*q[c]; w = t>1 ? t^5 : t) + lane-local sums. Phase B: unroll-4
// broadcast loop, 4 independent 128B fp16 gathers in flight.
__global__ void k_gat(const float* __restrict__ gat_b, const float* __restrict__ W2, int n) {
    int tid = threadIdx.x;
    int node = (blockIdx.x * blockDim.x + tid) >> 5;
    int lane = tid & 31;
    if (node >= n) return;
    bool head1 = lane >= 16;
    int ch = (lane & 15) * 2;
    const unsigned* hgu = (const unsigned*)g_hgh;

    float2 q = g_qs[node];
    float2 pself = g_ps[node];
    float t0 = pself.x * q.x, t1 = pself.y * q.y;
    float ws0 = t0 > 1.f ? pow5(t0) : t0;
    float ws1 = t1 > 1.f ? pow5(t1) : t1;
    float exs = head1 ? ws1 : ws0;

    unsigned hv = hgu[node * 32 + lane];
    float2 hf = __half22float2(*(const __half2*)&hv);
    float accx = exs * hf.x, accy = exs * hf.y;
    float acc2x = 0.f, acc2y = 0.f;
    float sA_acc = 0.f, sB_acc = 0.f;

    int off = g_off[node], deg = g_deg[node];
    for (int base = 0; base < deg; base += 32) {
        int cnt = min(32, deg - base);
        bool valid = lane < cnt;
        int r_l = g_csr[off + base + (valid ? lane : 0)];
        float2 pl = g_ps[r_l];
        float tA = pl.x * q.x, tB = pl.y * q.y;
        float exA = tA > 1.f ? pow5(tA) : tA;
        float exB = tB > 1.f ? pow5(tB) : tB;
        if (!valid) { exA = 0.f; exB = 0.f; }
        sA_acc += exA;
        sB_acc += exB;
        int k = 0;
        for (; k + 3 < cnt; k += 4) {
            int r0 = __shfl_sync(0xffffffffu, r_l, k);
            int r1 = __shfl_sync(0xffffffffu, r_l, k + 1);
            int r2 = __shfl_sync(0xffffffffu, r_l, k + 2);
            int r3 = __shfl_sync(0xffffffffu, r_l, k + 3);
            unsigned h0 = hgu[r0 * 32 + lane];
            unsigned h1 = hgu[r1 * 32 + lane];
            unsigned h2 = hgu[r2 * 32 + lane];
            unsigned h3 = hgu[r3 * 32 + lane];
            float wA0 = __shfl_sync(0xffffffffu, exA, k);
            float wB0 = __shfl_sync(0xffffffffu, exB, k);
            float wA1 = __shfl_sync(0xffffffffu, exA, k + 1);
            float wB1 = __shfl_sync(0xffffffffu, exB, k + 1);
            float wA2 = __shfl_sync(0xffffffffu, exA, k + 2);
            float wB2 = __shfl_sync(0xffffffffu, exB, k + 2);
            float wA3 = __shfl_sync(0xffffffffu, exA, k + 3);
            float wB3 = __shfl_sync(0xffffffffu, exB, k + 3);
            float w0 = head1 ? wB0 : wA0;
            float w1 = head1 ? wB1 : wA1;
            float w2 = head1 ? wB2 : wA2;
            float w3 = head1 ? wB3 : wA3;
            float2 f0 = __half22float2(*(const __half2*)&h0);
            float2 f1 = __half22float2(*(const __half2*)&h1);
            float2 f2 = __half22float2(*(const __half2*)&h2);
            float2 f3 = __half22float2(*(const __half2*)&h3);
            accx  = fmaf(w0, f0.x, accx);
            accy  = fmaf(w0, f0.y, accy);
            acc2x = fmaf(w1, f1.x, acc2x);
            acc2y = fmaf(w1, f1.y, acc2y);
            accx  = fmaf(w2, f2.x, accx);
            accy  = fmaf(w2, f2.y, accy);
            acc2x = fmaf(w3, f3.x, acc2x);
            acc2y = fmaf(w3, f3.y, acc2y);
        }
        for (; k < cnt; k++) {
            int r0 = __shfl_sync(0xffffffffu, r_l, k);
            float wA0 = __shfl_sync(0xffffffffu, exA, k);
            float wB0 = __shfl_sync(0xffffffffu, exB, k);
            float w0 = head1 ? wB0 : wA0;
            unsigned h0 = hgu[r0 * 32 + lane];
            float2 f0 = __half22float2(*(const __half2*)&h0);
            accx = fmaf(w0, f0.x, accx);
            accy = fmaf(w0, f0.y, accy);
        }
    }
#pragma unroll
    for (int o = 16; o; o >>= 1) {
        sA_acc += __shfl_xor_sync(0xffffffffu, sA_acc, o);
        sB_acc += __shfl_xor_sync(0xffffffffu, sB_acc, o);
    }
    float st = (head1 ? sB_acc : sA_acc) + exs;
    float vx = (accx + acc2x) / st;
    float vy = (accy + acc2y) / st;

    float ox = __shfl_down_sync(0xffffffffu, vx, 16);
    float oy = __shfl_down_sync(0xffffffffu, vy, 16);
    float c0 = fmaxf(fmaf(0.5f, vx + ox, gat_b[ch]),     0.f);
    float c1 = fmaxf(fmaf(0.5f, vy + oy, gat_b[ch + 1]), 0.f);
    float zi = fmaf(c0, W2[ch], c1 * W2[ch + 1]);
#pragma unroll
    for (int o = 8; o; o >>= 1)
        zi += __shfl_down_sync(0xffffffffu, zi, o);
    if (lane == 0) g_z[node] = g_dinv[node] * zi;
}

// launch 7: warp/node GCN2 gather + output; tail-resets deg
__global__ void k_gcn2(float* __restrict__ out, const float* __restrict__ b2, int n) {
    int tid = threadIdx.x;
    int gid = blockIdx.x * blockDim.x + tid;
    int node = gid >> 5;
    int lane = tid & 31;
    if (node >= n) return;
    float s = (lane == 0) ? g_z[node] : 0.f;
    int off = g_off[node], end = off + g_deg[node];
    for (int j = off + lane; j < end; j += 32)
        s += g_z[g_csr[j]];
#pragma unroll
    for (int o = 16; o; o >>= 1)
        s += __shfl_down_sync(0xffffffffu, s, o);
    if (lane == 0) {
        out[node] = fmaf(g_dinv[node], s, b2[0]);
        g_deg[node] = 0;
    }
}

// ---------------- launch ----------------
extern "C" void kernel_launch(void* const* d_in, const int* in_sizes, int n_in,
                              void* d_out, int out_size) {
    const float* x    = (const float*)d_in[0];
    const void*  ei   = d_in[1];
    const float* W1   = (const float*)d_in[2];
    const float* b1   = (const float*)d_in[3];
    const float* Wg   = (const float*)d_in[4];
    const float* attS = (const float*)d_in[5];
    const float* attD = (const float*)d_in[6];
    const float* gb   = (const float*)d_in[7];
    const float* W2   = (const float*)d_in[8];
    const float* b2   = (const float*)d_in[9];
    float* out = (float*)d_out;

    int n = in_sizes[0] / 2;
    int E = in_sizes[1] / 2;
    const int T = 256;
    int nb = (n + 1023) / 1024;

    k_degcount<<<(E + T - 1) / T, T>>>(ei, E);
    k_scan1<<<nb, 1024>>>(n);
    k_scan23<<<nb, 1024>>>(x, n, nb);
    k_fill<<<(E + T - 1) / T, T>>>(ei, E);
    k_layer1<<<(n * 32 + T - 1) / T, T>>>(W1, b1, Wg, attS, attD, n);
    k_gat<<<(n * 32 + T - 1) / T, T>>>(gb, W2, n);
    k_gcn2<<<(n * 32 + T - 1) / T, T>>>(out, b2, n);
}

// round 14
// speedup vs baseline: 1.0114x; 1.0114x over previous
#include <cuda_runtime.h>
#include <cuda_fp16.h>
#include <cuda_bf16.h>

// RoadGNN: GCN(2->32) -> ReLU -> GAT(32->2x32, mean heads) -> ReLU -> GCN(32->1)
// Counting-sort CSR (rank precomputed in degree pass -> atomic-free fill),
// 2 edges/thread vectorized edge passes, GCN1 in input space, factored-exp GAT
// weights (zero MUFU in edge loops), fp16 feature gathers.

#define MAXN 100000
#define MAXE 1600000
#define MAXEP (MAXE + 3 * MAXN + 32)

// ---------------- scratch ----------------
__device__ int      g_deg[MAXN];        // zeroed by k_gcn2 tail each call
__device__ int      g_off[MAXN];
__device__ __align__(8) int g_pos[MAXE]; // per-edge rank within its dst bucket
__device__ __align__(16) int g_csr[MAXEP];
__device__ int      g_bsum[128];
__device__ float    g_dinv[MAXN];
__device__ __align__(8) float2 g_xt[MAXN];   // dinv[n] * x[n]
__device__ __half   g_hgh[MAXN * 64];        // GAT linear out fp16 (h0|h1)
__device__ __align__(8) float2 g_ps[MAXN];   // exp(0.2*a_src) per head
__device__ __align__(8) float2 g_qs[MAXN];   // exp(0.2*a_dst) per head
__device__ float    g_z[MAXN];

// ---------------- helpers ----------------
__device__ __forceinline__ float pow5(float t) { float t2 = t * t; return t2 * t2 * t; }
__device__ __forceinline__ int block_is64(const int* ei32, int* sh) {
    if (threadIdx.x < 32) {
        int bad = (ei32[2 * threadIdx.x + 1] != 0);
        unsigned b = __ballot_sync(0xffffffffu, bad);
        if (threadIdx.x == 0) *sh = (b == 0u);
    }
    __syncthreads();
    return *sh;
}

// ---------------- kernels ----------------

// launch 1: in-degree count + rank, 2 edges/thread
__global__ void k_degcount(const void* __restrict__ ei, int E) {
    __shared__ int sh;
    int is64 = block_is64((const int*)ei, &sh);
    int g = blockIdx.x * blockDim.x + threadIdx.x;
    int e = 2 * g;
    if (e >= E) return;
    int c0, c1 = -1;
    if (is64) {
        const long long* p = (const long long*)ei;
        if (e + 1 < E) {
            longlong2 cc = *(const longlong2*)&p[E + e];
            c0 = (int)cc.x; c1 = (int)cc.y;
        } else c0 = (int)p[E + e];
    } else {
        const int* p = (const int*)ei;
        if (e + 1 < E) {
            int2 cc = *(const int2*)&p[E + e];
            c0 = cc.x; c1 = cc.y;
        } else c0 = p[E + e];
    }
    if (c1 >= 0) {
        int2 pp;
        pp.x = atomicAdd(&g_deg[c0], 1);
        pp.y = atomicAdd(&g_deg[c1], 1);
        *(int2*)&g_pos[e] = pp;
    } else {
        g_pos[e] = atomicAdd(&g_deg[c0], 1);
    }
}

// launch 2: block-local scan of 4-padded degrees
__global__ void k_scan1(int n) {
    __shared__ int sh[1024];
    int tid = threadIdx.x;
    int i = blockIdx.x * 1024 + tid;
    int v = (i < n) ? ((g_deg[i] + 3) & ~3) : 0;
    sh[tid] = v;
    __syncthreads();
#pragma unroll
    for (int d = 1; d < 1024; d <<= 1) {
        int t = (tid >= d) ? sh[tid - d] : 0;
        __syncthreads();
        sh[tid] += t;
        __syncthreads();
    }
    if (i < n) g_off[i] = sh[tid] - v;
    if (tid == 1023) g_bsum[blockIdx.x] = sh[1023];
}

// launch 3: finish scan; compute dinv + xt
__global__ void k_scan23(const float* __restrict__ x, int n, int nb) {
    __shared__ int spre;
    int tid = threadIdx.x;
    if (tid < 32) {
        int p = 0;
        for (int k = tid; k < blockIdx.x; k += 32) p += g_bsum[k];
#pragma unroll
        for (int o = 16; o; o >>= 1) p += __shfl_down_sync(0xffffffffu, p, o);
        if (tid == 0) spre = p;
    }
    __syncthreads();
    int i = blockIdx.x * 1024 + tid;
    if (i < n) {
        g_off[i] += spre;
        float d = rsqrtf((float)(g_deg[i] + 1));
        g_dinv[i] = d;
        float2 xv = *(const float2*)&x[2 * i];
        g_xt[i] = make_float2(d * xv.x, d * xv.y);
    }
}

// launch 4 (ncu slot): CSR fill — no atomics, 2 edges/thread
__global__ void k_fill(const void* __restrict__ ei, int E) {
    __shared__ int sh;
    int is64 = block_is64((const int*)ei, &sh);
    int g = blockIdx.x * blockDim.x + threadIdx.x;
    int e = 2 * g;
    if (e >= E) return;
    int r0, c0, r1 = -1, c1 = -1;
    if (is64) {
        const long long* p = (const long long*)ei;
        if (e + 1 < E) {
            longlong2 rr = *(const longlong2*)&p[e];
            longlong2 cc = *(const longlong2*)&p[E + e];
            r0 = (int)rr.x; r1 = (int)rr.y;
            c0 = (int)cc.x; c1 = (int)cc.y;
        } else { r0 = (int)p[e]; c0 = (int)p[E + e]; }
    } else {
        const int* p = (const int*)ei;
        if (e + 1 < E) {
            int2 rr = *(const int2*)&p[e];
            int2 cc = *(const int2*)&p[E + e];
            r0 = rr.x; r1 = rr.y;
            c0 = cc.x; c1 = cc.y;
        } else { r0 = p[e]; c0 = p[E + e]; }
    }
    if (r1 >= 0) {
        int2 pp = *(const int2*)&g_pos[e];
        g_csr[g_off[c0] + pp.x] = r0;
        g_csr[g_off[c1] + pp.y] = r1;
    } else {
        g_csr[g_off[c0] + g_pos[e]] = r0;
    }
}

// launch 5: warp/node. Lane-parallel xt gather (GCN1 in input space),
// h1 = relu(dinv*(agg@W1)+b1), GAT linear, p/q exp factors.
__global__ void k_layer1(const float* __restrict__ W1, const float* __restrict__ b1,
                         const float* __restrict__ Wg,
                         const float* __restrict__ attS, const float* __restrict__ attD, int n) {
    __shared__ float sWg[32 * 64];
    int tid = threadIdx.x;
    for (int i = tid; i < 2048; i += blockDim.x) sWg[i] = Wg[i];
    __syncthreads();

    int node = (blockIdx.x * blockDim.x + tid) >> 5;
    int lane = tid & 31;
    if (node >= n) return;

    int off = g_off[node], deg = g_deg[node];
    float ax = 0.f, ay = 0.f;
    for (int base = 0; base < deg; base += 32) {
        if (base + lane < deg) {
            int r = g_csr[off + base + lane];
            float2 v = g_xt[r];
            ax += v.x; ay += v.y;
        }
    }
#pragma unroll
    for (int o = 16; o; o >>= 1) {
        ax += __shfl_xor_sync(0xffffffffu, ax, o);
        ay += __shfl_xor_sync(0xffffffffu, ay, o);
    }
    float2 self = g_xt[node];
    float d = g_dinv[node];
    ax = d * (ax + self.x);
    ay = d * (ay + self.y);

    float h1 = fmaxf(fmaf(ax, W1[lane], fmaf(ay, W1[32 + lane], b1[lane])), 0.f);

    float o0 = 0.f, o1 = 0.f;
#pragma unroll
    for (int i = 0; i < 32; i++) {
        float hv = __shfl_sync(0xffffffffu, h1, i);
        o0 = fmaf(hv, sWg[i * 64 + lane], o0);
        o1 = fmaf(hv, sWg[i * 64 + 32 + lane], o1);
    }
    g_hgh[node * 64 + lane]      = __float2half(o0);
    g_hgh[node * 64 + 32 + lane] = __float2half(o1);

    float as0 = o0 * attS[lane];
    float as1 = o1 * attS[32 + lane];
    float ad0 = o0 * attD[lane];
    float ad1 = o1 * attD[32 + lane];
#pragma unroll
    for (int o = 16; o; o >>= 1) {
        as0 += __shfl_down_sync(0xffffffffu, as0, o);
        as1 += __shfl_down_sync(0xffffffffu, as1, o);
        ad0 += __shfl_down_sync(0xffffffffu, ad0, o);
        ad1 += __shfl_down_sync(0xffffffffu, ad1, o);
    }
    if (lane == 0) {
        g_ps[node] = make_float2(__expf(0.2f * as0), __expf(0.2f * as1));
        g_qs[node] = make_float2(__expf(0.2f * ad0), __expf(0.2f * ad1));
    }
}

// launch 6: warp/node GAT. Phase A: lane-parallel multiplicative weights
// (t = p[r]*q[c]; w = t>1 ? t^5 : t) + lane-local sums. Phase B: unroll-4
// broadcast loop, 4 independent 128B fp16 gathers in flight.
__global__ void k_gat(const float* __restrict__ gat_b, const float* __restrict__ W2, int n) {
    int tid = threadIdx.x;
    int node = (blockIdx.x * blockDim.x + tid) >> 5;
    int lane = tid & 31;
    if (node >= n) return;
    bool head1 = lane >= 16;
    int ch = (lane & 15) * 2;
    const unsigned* hgu = (const unsigned*)g_hgh;

    float2 q = g_qs[node];
    float2 pself = g_ps[node];
    float t0 = pself.x * q.x, t1 = pself.y * q.y;
    float ws0 = t0 > 1.f ? pow5(t0) : t0;
    float ws1 = t1 > 1.f ? pow5(t1) : t1;
    float exs = head1 ? ws1 : ws0;

    unsigned hv = hgu[node * 32 + lane];
    float2 hf = __half22float2(*(const __half2*)&hv);
    float accx = exs * hf.x, accy = exs * hf.y;
    float acc2x = 0.f, acc2y = 0.f;
    float sA_acc = 0.f, sB_acc = 0.f;

    int off = g_off[node], deg = g_deg[node];
    for (int base = 0; base < deg; base += 32) {
        int cnt = min(32, deg - base);
        bool valid = lane < cnt;
        int r_l = g_csr[off + base + (valid ? lane : 0)];
        float2 pl = g_ps[r_l];
        float tA = pl.x * q.x, tB = pl.y * q.y;
        float exA = tA > 1.f ? pow5(tA) : tA;
        float exB = tB > 1.f ? pow5(tB) : tB;
        if (!valid) { exA = 0.f; exB = 0.f; }
        sA_acc += exA;
        sB_acc += exB;
        int k = 0;
        for (; k + 3 < cnt; k += 4) {
            int r0 = __shfl_sync(0xffffffffu, r_l, k);
            int r1 = __shfl_sync(0xffffffffu, r_l, k + 1);
            int r2 = __shfl_sync(0xffffffffu, r_l, k + 2);
            int r3 = __shfl_sync(0xffffffffu, r_l, k + 3);
            unsigned h0 = hgu[r0 * 32 + lane];
            unsigned h1 = hgu[r1 * 32 + lane];
            unsigned h2 = hgu[r2 * 32 + lane];
            unsigned h3 = hgu[r3 * 32 + lane];
            float wA0 = __shfl_sync(0xffffffffu, exA, k);
            float wB0 = __shfl_sync(0xffffffffu, exB, k);
            float wA1 = __shfl_sync(0xffffffffu, exA, k + 1);
            float wB1 = __shfl_sync(0xffffffffu, exB, k + 1);
            float wA2 = __shfl_sync(0xffffffffu, exA, k + 2);
            float wB2 = __shfl_sync(0xffffffffu, exB, k + 2);
            float wA3 = __shfl_sync(0xffffffffu, exA, k + 3);
            float wB3 = __shfl_sync(0xffffffffu, exB, k + 3);
            float w0 = head1 ? wB0 : wA0;
            float w1 = head1 ? wB1 : wA1;
            float w2 = head1 ? wB2 : wA2;
            float w3 = head1 ? wB3 : wA3;
            float2 f0 = __half22float2(*(const __half2*)&h0);
            float2 f1 = __half22float2(*(const __half2*)&h1);
            float2 f2 = __half22float2(*(const __half2*)&h2);
            float2 f3 = __half22float2(*(const __half2*)&h3);
            accx  = fmaf(w0, f0.x, accx);
            accy  = fmaf(w0, f0.y, accy);
            acc2x = fmaf(w1, f1.x, acc2x);
            acc2y = fmaf(w1, f1.y, acc2y);
            accx  = fmaf(w2, f2.x, accx);
            accy  = fmaf(w2, f2.y, accy);
            acc2x = fmaf(w3, f3.x, acc2x);
            acc2y = fmaf(w3, f3.y, acc2y);
        }
        for (; k < cnt; k++) {
            int r0 = __shfl_sync(0xffffffffu, r_l, k);
            float wA0 = __shfl_sync(0xffffffffu, exA, k);
            float wB0 = __shfl_sync(0xffffffffu, exB, k);
            float w0 = head1 ? wB0 : wA0;
            unsigned h0 = hgu[r0 * 32 + lane];
            float2 f0 = __half22float2(*(const __half2*)&h0);
            accx = fmaf(w0, f0.x, accx);
            accy = fmaf(w0, f0.y, accy);
        }
    }
#pragma unroll
    for (int o = 16; o; o >>= 1) {
        sA_acc += __shfl_xor_sync(0xffffffffu, sA_acc, o);
        sB_acc += __shfl_xor_sync(0xffffffffu, sB_acc, o);
    }
    float st = (head1 ? sB_acc : sA_acc) + exs;
    float vx = (accx + acc2x) / st;
    float vy = (accy + acc2y) / st;

    float ox = __shfl_down_sync(0xffffffffu, vx, 16);
    float oy = __shfl_down_sync(0xffffffffu, vy, 16);
    float c0 = fmaxf(fmaf(0.5f, vx + ox, gat_b[ch]),     0.f);
    float c1 = fmaxf(fmaf(0.5f, vy + oy, gat_b[ch + 1]), 0.f);
    float zi = fmaf(c0, W2[ch], c1 * W2[ch + 1]);
#pragma unroll
    for (int o = 8; o; o >>= 1)
        zi += __shfl_down_sync(0xffffffffu, zi, o);
    if (lane == 0) g_z[node] = g_dinv[node] * zi;
}

// launch 7: warp/node GCN2 gather + output; tail-resets deg
__global__ void k_gcn2(float* __restrict__ out, const float* __restrict__ b2, int n) {
    int tid = threadIdx.x;
    int gid = blockIdx.x * blockDim.x + tid;
    int node = gid >> 5;
    int lane = tid & 31;
    if (node >= n) return;
    float s = (lane == 0) ? g_z[node] : 0.f;
    int off = g_off[node], end = off + g_deg[node];
    for (int j = off + lane; j < end; j += 32)
        s += g_z[g_csr[j]];
#pragma unroll
    for (int o = 16; o; o >>= 1)
        s += __shfl_down_sync(0xffffffffu, s, o);
    if (lane == 0) {
        out[node] = fmaf(g_dinv[node], s, b2[0]);
        g_deg[node] = 0;
    }
}

// ---------------- launch ----------------
extern "C" void kernel_launch(void* const* d_in, const int* in_sizes, int n_in,
                              void* d_out, int out_size) {
    const float* x    = (const float*)d_in[0];
    const void*  ei   = d_in[1];
    const float* W1   = (const float*)d_in[2];
    const float* b1   = (const float*)d_in[3];
    const float* Wg   = (const float*)d_in[4];
    const float* attS = (const float*)d_in[5];
    const float* attD = (const float*)d_in[6];
    const float* gb   = (const float*)d_in[7];
    const float* W2   = (const float*)d_in[8];
    const float* b2   = (const float*)d_in[9];
    float* out = (float*)d_out;

    int n = in_sizes[0] / 2;
    int E = in_sizes[1] / 2;
    const int T = 256;
    int nb = (n + 1023) / 1024;
    int Eh = (E + 1) / 2;

    k_degcount<<<(Eh + T - 1) / T, T>>>(ei, E);
    k_scan1<<<nb, 1024>>>(n);
    k_scan23<<<nb, 1024>>>(x, n, nb);
    k_fill<<<(Eh + T - 1) / T, T>>>(ei, E);
    k_layer1<<<(n * 32 + T - 1) / T, T>>>(W1, b1, Wg, attS, attD, n);
    k_gat<<<(n * 32 + T - 1) / T, T>>>(gb, W2, n);
    k_gcn2<<<(n * 32 + T - 1) / T, T>>>(out, b2, n);
}